// round 5
// baseline (speedup 1.0000x reference)
#include <cuda_runtime.h>
#include <cstdint>

// Problem constants
#define BB 16
#define LL 512
#define DD 768
#define HH 12
#define UU 384
#define NH 6
#define HD 64
#define KP 384
#define RR 128        // L - K  (merged count == unpreserved count)
#define LH 256        // L/2
#define OT 386        // output tokens per batch

// ---------------- device scratch (static, allocation-free) ----------------
__device__ float              g_imp[BB * LL];
__device__ float              g_invn[BB * LL];
__device__ int                g_unp[BB * RR];
__device__ unsigned long long g_nodekey[BB * LH];
__device__ int                g_srctok[BB * RR];
__device__ int                g_dstj[BB * RR];
__device__ int                g_unm[BB * RR];
__device__ float              g_counts[BB * LH];
__device__ float              g_q[BB * UU];
__device__ float              g_m[BB * NH * DD];
__device__ float              g_cb[BB * NH];
__device__ float              g_logits[BB * NH * RR];
__device__ float              g_y[BB * NH * DD];
__device__ float              g_ctx[BB * UU];

__device__ __forceinline__ unsigned ford(float f) {
    unsigned u = __float_as_uint(f);
    return (u & 0x80000000u) ? ~u : (u | 0x80000000u);
}

// ---------------- K0: init accumulators (must run every replay) -----------
__global__ void k_init() {
    int i = blockIdx.x * blockDim.x + threadIdx.x;
    if (i < BB * LL) g_imp[i] = 0.f;
    if (i < BB * LH) { g_nodekey[i] = 0ull; g_counts[i] = 1.0f; }
}

// ---------------- K2: importance = column sums, diag removed --------------
// grid (8 row-chunks, 12 heads, 16 batch), 128 threads (4 cols each, float4)
__global__ void k_importance(const float* __restrict__ sc) {
    int b = blockIdx.z, h = blockIdx.y, chunk = blockIdx.x;
    int j0 = threadIdx.x * 4;
    const float* base = sc + (((size_t)b * HH + h) * LL + (size_t)chunk * 64) * LL;
    int i0 = chunk * 64;
    float a0 = 0.f, a1 = 0.f, a2 = 0.f, a3 = 0.f;
#pragma unroll 4
    for (int i = 0; i < 64; i++) {
        float4 v = *(const float4*)(base + (size_t)i * LL + j0);
        int gi = i0 + i;
        if (gi == j0)     v.x = 0.f;
        if (gi == j0 + 1) v.y = 0.f;
        if (gi == j0 + 2) v.z = 0.f;
        if (gi == j0 + 3) v.w = 0.f;
        a0 += v.x; a1 += v.y; a2 += v.z; a3 += v.w;
    }
    float* ip = g_imp + b * LL + j0;
    atomicAdd(ip + 0, a0); atomicAdd(ip + 1, a1);
    atomicAdd(ip + 2, a2); atomicAdd(ip + 3, a3);
}

// ---------------- K1: per-token inverse L2 norms ---------------------------
// grid (64, 16), 256 threads: one warp per row
__global__ void k_invnorm(const float* __restrict__ hid) {
    int warp = threadIdx.x >> 5, lane = threadIdx.x & 31;
    int row = blockIdx.x * 8 + warp;
    int b = blockIdx.y;
    const float4* p = (const float4*)(hid + ((size_t)b * LL + row) * DD);
    float s = 0.f;
#pragma unroll
    for (int it = 0; it < 6; it++) {
        float4 v = p[lane + it * 32];
        s += v.x * v.x + v.y * v.y + v.z * v.z + v.w * v.w;
    }
    for (int off = 16; off; off >>= 1) s += __shfl_xor_sync(0xffffffffu, s, off);
    if (lane == 0) g_invn[b * LL + row] = rsqrtf(s);
}

// ---------------- K3: top-K mask -> unpreserved idx (ascending) ------------
// grid 16, 512 threads. Rank-by-count with index tiebreak == lax.top_k.
__global__ void k_topk() {
    int b = blockIdx.x, t = threadIdx.x;
    __shared__ unsigned long long keys[LL];
    __shared__ int flags[LL];
    float v = g_imp[b * LL + t];
    unsigned long long key = ((unsigned long long)ford(v) << 32) | (unsigned)(0xFFFFFFFFu - t);
    keys[t] = key;
    __syncthreads();
    int rank = 0;
    for (int x = 0; x < LL; x++) rank += (keys[x] > key);
    int unp = (rank >= KP) ? 1 : 0;
    flags[t] = unp;
    __syncthreads();
    if (unp) {
        int pos = 0;
        for (int x = 0; x < t; x++) pos += flags[x];
        g_unp[b * RR + pos] = t;
    }
}

// ---------------- K4: cosine-sim GEMM + row max/argmax ---------------------
// C[i][j] = <na_i, nb_j>, a = even tokens, b = odd tokens, pre-normalized at
// smem-store time. 64x64 tile, 256 threads, 4x4 micro-tile (FP32 for exact
// rank preservation). Row argmax folded via packed atomicMax.
__global__ void k_sim(const float* __restrict__ hid) {
    int b = blockIdx.z, i0 = blockIdx.y * 64, j0 = blockIdx.x * 64;
    __shared__ float As[16][68];
    __shared__ float Bs[16][68];
    int tid = threadIdx.x;
    int tx = tid & 15, ty = tid >> 4;
    int lrow = tid >> 2, lseg = tid & 3;
    const float* base = hid + (size_t)b * LL * DD;
    float ia = g_invn[b * LL + 2 * (i0 + lrow)];
    float ib = g_invn[b * LL + 2 * (j0 + lrow) + 1];
    const float* arow = base + (size_t)(2 * (i0 + lrow)) * DD + lseg * 4;
    const float* brow = base + (size_t)(2 * (j0 + lrow) + 1) * DD + lseg * 4;

    float acc[4][4] = {};
    for (int k0 = 0; k0 < DD; k0 += 16) {
        float4 av = *(const float4*)(arow + k0);
        float4 bv = *(const float4*)(brow + k0);
        __syncthreads();
        As[lseg * 4 + 0][lrow] = av.x * ia;
        As[lseg * 4 + 1][lrow] = av.y * ia;
        As[lseg * 4 + 2][lrow] = av.z * ia;
        As[lseg * 4 + 3][lrow] = av.w * ia;
        Bs[lseg * 4 + 0][lrow] = bv.x * ib;
        Bs[lseg * 4 + 1][lrow] = bv.y * ib;
        Bs[lseg * 4 + 2][lrow] = bv.z * ib;
        Bs[lseg * 4 + 3][lrow] = bv.w * ib;
        __syncthreads();
#pragma unroll
        for (int kk = 0; kk < 16; kk++) {
            float a[4], c[4];
            *(float4*)a = *(const float4*)&As[kk][ty * 4];
            *(float4*)c = *(const float4*)&Bs[kk][tx * 4];
#pragma unroll
            for (int r = 0; r < 4; r++)
#pragma unroll
                for (int q = 0; q < 4; q++) acc[r][q] += a[r] * c[q];
        }
    }
    // per-row max/argmax (tie -> smaller j, matching jnp.argmax)
#pragma unroll
    for (int r = 0; r < 4; r++) {
        float best = acc[r][0]; int bc = 0;
        if (acc[r][1] > best) { best = acc[r][1]; bc = 1; }
        if (acc[r][2] > best) { best = acc[r][2]; bc = 2; }
        if (acc[r][3] > best) { best = acc[r][3]; bc = 3; }
        int j = j0 + tx * 4 + bc;
        unsigned long long key = ((unsigned long long)ford(best) << 32) | (unsigned)(255 - j);
        for (int off = 8; off; off >>= 1) {
            unsigned long long o = __shfl_xor_sync(0xffffffffu, key, off);
            if (o > key) key = o;
        }
        if (tx == 0) atomicMax(&g_nodekey[b * LH + i0 + ty * 4 + r], key);
    }
}

// ---------------- K5: stable descending edge argsort via rank counting -----
// grid 16, 256 threads. rank<128 -> src (position = rank), else unm.
__global__ void k_edges() {
    int b = blockIdx.x, i = threadIdx.x;
    __shared__ unsigned long long ek[LH];
    unsigned long long nk = g_nodekey[b * LH + i];
    int nidx = 255 - (int)(unsigned)(nk & 0xFFFFFFFFull);
    unsigned long long key = (nk & 0xFFFFFFFF00000000ull) | (unsigned)(255 - i);
    ek[i] = key;
    __syncthreads();
    int rank = 0;
    for (int x = 0; x < LH; x++) rank += (ek[x] > key);
    if (rank < RR) {
        g_srctok[b * RR + rank] = i;
        g_dstj[b * RR + rank] = nidx;
        atomicAdd(&g_counts[b * LH + nidx], 1.0f);
    } else {
        g_unm[b * RR + (rank - RR)] = i;
    }
}

// ---------------- K6: assemble output ---------------------------------------
__global__ void k_zero_dst(float* __restrict__ out) {
    int b = blockIdx.y, j = blockIdx.x;
    ((float4*)(out + ((size_t)b * OT + 129 + j) * DD))[threadIdx.x] = make_float4(0.f, 0.f, 0.f, 0.f);
}

__global__ void k_copy(const float* __restrict__ hid, float* __restrict__ out) {
    int b = blockIdx.y, v = blockIdx.x;                  // 0..128
    int srow = (v == 0) ? 0 : 2 * g_unm[b * RR + (v - 1)];
    const float4* s = (const float4*)(hid + ((size_t)b * LL + srow) * DD);
    float4* d = (float4*)(out + ((size_t)b * OT + v) * DD);
    d[threadIdx.x] = s[threadIdx.x];
}

__global__ void k_scatter(const float* __restrict__ hid, float* __restrict__ out) {
    int b = blockIdx.y, p = blockIdx.x;                  // 0..127
    int s = g_srctok[b * RR + p], dj = g_dstj[b * RR + p];
    const float* src = hid + ((size_t)b * LL + 2 * s) * DD;
    float* dst = out + ((size_t)b * OT + 129 + dj) * DD;
    int d0 = threadIdx.x * 4;
    float4 v = *(const float4*)(src + d0);
    atomicAdd(dst + d0 + 0, v.x);
    atomicAdd(dst + d0 + 1, v.y);
    atomicAdd(dst + d0 + 2, v.z);
    atomicAdd(dst + d0 + 3, v.w);
}

__global__ void k_merge(const float* __restrict__ hid, float* __restrict__ out) {
    int b = blockIdx.y, j = blockIdx.x;                  // 0..255
    float c = g_counts[b * LH + j];
    int d0 = threadIdx.x * 4;
    float* o = out + ((size_t)b * OT + 129 + j) * DD + d0;
    float4 a = *(float4*)o;
    float4 x = *(const float4*)(hid + ((size_t)b * LL + 2 * j + 1) * DD + d0);
    a.x = (a.x + x.x) / c; a.y = (a.y + x.y) / c;
    a.z = (a.z + x.z) / c; a.w = (a.w + x.w) / c;
    *(float4*)o = a;
}

// ---------------- attention (refactored) ------------------------------------
// q = cls @ Wq + bq        grid 16, 384 threads
__global__ void k_q(const float* __restrict__ hid, const float* __restrict__ Wq,
                    const float* __restrict__ bq) {
    int b = blockIdx.x, u = threadIdx.x;
    __shared__ float cls[DD];
    cls[u] = hid[(size_t)b * LL * DD + u];
    cls[u + UU] = hid[(size_t)b * LL * DD + UU + u];
    __syncthreads();
    float a0 = bq[u], a1 = 0.f;
#pragma unroll 4
    for (int k = 0; k < DD; k += 2) {
        a0 += cls[k] * Wq[(size_t)k * UU + u];
        a1 += cls[k + 1] * Wq[(size_t)(k + 1) * UU + u];
    }
    g_q[b * UU + u] = a0 + a1;
}

// m[b,h,:] = Wk_h @ q_h ; cbias = q_h . bk_h     grid (6,16), 768 threads
__global__ void k_m(const float* __restrict__ Wk, const float* __restrict__ bk) {
    int h = blockIdx.x, b = blockIdx.y, t = threadIdx.x;
    __shared__ float sq[HD];
    __shared__ float sp[HD];
    if (t < HD) sq[t] = g_q[b * UU + h * HD + t];
    __syncthreads();
    float acc = 0.f;
    const float* wrow = Wk + (size_t)t * UU + h * HD;
#pragma unroll
    for (int u = 0; u < HD; u += 4) {
        float4 wv = *(const float4*)(wrow + u);
        acc += wv.x * sq[u] + wv.y * sq[u + 1] + wv.z * sq[u + 2] + wv.w * sq[u + 3];
    }
    g_m[((size_t)b * NH + h) * DD + t] = acc;
    if (t < HD) sp[t] = sq[t] * bk[h * HD + t];
    __syncthreads();
    if (t == 0) {
        float c = 0.f;
        for (int u = 0; u < HD; u++) c += sp[u];
        g_cb[b * NH + h] = c;
    }
}

// logits[b,h,t] = (x_t . m_bh + cbias) / 8      one warp per (b,t)
__global__ void k_logits(const float* __restrict__ hid) {
    int w = (blockIdx.x * blockDim.x + threadIdx.x) >> 5;
    int lane = threadIdx.x & 31;
    if (w >= BB * RR) return;
    int b = w >> 7, t = w & 127;
    int row = g_unp[b * RR + t];
    const float* x = hid + ((size_t)b * LL + row) * DD;
    const float* m = g_m + (size_t)b * NH * DD;
    float acc[NH] = {};
    for (int k = lane; k < DD; k += 32) {
        float xv = x[k];
#pragma unroll
        for (int h = 0; h < NH; h++) acc[h] += xv * m[h * DD + k];
    }
#pragma unroll
    for (int h = 0; h < NH; h++)
        for (int off = 16; off; off >>= 1) acc[h] += __shfl_xor_sync(0xffffffffu, acc[h], off);
    if (lane == 0) {
#pragma unroll
        for (int h = 0; h < NH; h++)
            g_logits[((size_t)b * NH + h) * RR + t] = (acc[h] + g_cb[b * NH + h]) * 0.125f;
    }
}

// softmax over 128 keys, then y[b,h,:] = sum_t w_t * x_t   grid (6,16), 256 thr
__global__ void k_smax_y(const float* __restrict__ hid) {
    int h = blockIdx.x, b = blockIdx.y, t = threadIdx.x;
    __shared__ float w[RR];
    __shared__ int su[RR];
    __shared__ float red[8];
    if (t < RR) {
        w[t] = g_logits[((size_t)b * NH + h) * RR + t];
        su[t] = g_unp[b * RR + t];
    }
    __syncthreads();
    if (t < RR) {
        float m = w[t];
        for (int off = 16; off; off >>= 1) m = fmaxf(m, __shfl_xor_sync(0xffffffffu, m, off));
        if ((t & 31) == 0) red[t >> 5] = m;
    }
    __syncthreads();
    float mx = fmaxf(fmaxf(red[0], red[1]), fmaxf(red[2], red[3]));
    float e = 0.f;
    if (t < RR) e = expf(w[t] - mx);
    float s = e;
    for (int off = 16; off; off >>= 1) s += __shfl_xor_sync(0xffffffffu, s, off);
    if (t < RR && (t & 31) == 0) red[4 + (t >> 5)] = s;
    __syncthreads();
    float tot = red[4] + red[5] + red[6] + red[7];
    if (t < RR) w[t] = e / tot;
    __syncthreads();
    for (int d = t; d < DD; d += 256) {
        float acc = 0.f;
#pragma unroll 4
        for (int tt = 0; tt < RR; tt++)
            acc += w[tt] * hid[((size_t)b * LL + su[tt]) * DD + d];
        g_y[((size_t)b * NH + h) * DD + d] = acc;
    }
}

// ctx[b,u] = y[b,h(u),:] . Wv[:,u] + bv[u]    grid 16, 384 threads
__global__ void k_ctx(const float* __restrict__ Wv, const float* __restrict__ bv) {
    int b = blockIdx.x, u = threadIdx.x;
    __shared__ float sy[NH * DD];
    for (int i = u; i < NH * DD; i += UU) sy[i] = g_y[(size_t)b * NH * DD + i];
    __syncthreads();
    int h = u >> 6;
    float acc = bv[u];
#pragma unroll 4
    for (int d = 0; d < DD; d++) acc += sy[h * DD + d] * Wv[(size_t)d * UU + u];
    g_ctx[b * UU + u] = acc;
}

// new_token = ctx @ Wo + bo -> out row 385    grid 16, 768 threads
__global__ void k_newtok(const float* __restrict__ Wo, const float* __restrict__ bo,
                         float* __restrict__ out) {
    int b = blockIdx.x, d = threadIdx.x;
    __shared__ float sc[UU];
    if (d < UU) sc[d] = g_ctx[b * UU + d];
    __syncthreads();
    float acc = bo[d];
#pragma unroll 4
    for (int u = 0; u < UU; u++) acc += sc[u] * Wo[(size_t)u * DD + d];
    out[((size_t)b * OT + 385) * DD + d] = acc;
}

// ---------------- launch ----------------------------------------------------
extern "C" void kernel_launch(void* const* d_in, const int* in_sizes, int n_in,
                              void* d_out, int out_size) {
    (void)in_sizes; (void)n_in; (void)out_size;
    const float* hid = (const float*)d_in[0];
    const float* sc  = (const float*)d_in[1];
    const float* Wq  = (const float*)d_in[2];
    const float* bq  = (const float*)d_in[3];
    const float* Wk  = (const float*)d_in[4];
    const float* bk  = (const float*)d_in[5];
    const float* Wv  = (const float*)d_in[6];
    const float* bv  = (const float*)d_in[7];
    const float* Wo  = (const float*)d_in[8];
    const float* bo  = (const float*)d_in[9];
    float* out = (float*)d_out;

    k_init<<<32, 256>>>();
    k_importance<<<dim3(8, HH, BB), 128>>>(sc);
    k_invnorm<<<dim3(64, BB), 256>>>(hid);
    k_topk<<<BB, 512>>>();
    k_sim<<<dim3(4, 4, BB), 256>>>(hid);
    k_edges<<<BB, 256>>>();
    k_zero_dst<<<dim3(LH, BB), 192>>>(out);
    k_copy<<<dim3(129, BB), 192>>>(hid, out);
    k_scatter<<<dim3(RR, BB), 192>>>(hid, out);
    k_merge<<<dim3(LH, BB), 192>>>(hid, out);
    k_q<<<BB, UU>>>(hid, Wq, bq);
    k_m<<<dim3(NH, BB), DD>>>(Wk, bk);
    k_logits<<<256, 256>>>(hid);
    k_smax_y<<<dim3(NH, BB), 256>>>(hid);
    k_ctx<<<BB, UU>>>(Wv, bv);
    k_newtok<<<BB, DD>>>(Wo, bo, out);
}

// round 6
// speedup vs baseline: 1.0026x; 1.0026x over previous
#include <cuda_runtime.h>
#include <cstdint>

// Problem constants
#define BB 16
#define LL 512
#define DD 768
#define HH 12
#define UU 384
#define NH 6
#define HD 64
#define KP 384
#define RR 128        // L - K  (merged count == unpreserved count)
#define LH 256        // L/2
#define OT 386        // output tokens per batch

// ---------------- device scratch (static, allocation-free) ----------------
__device__ float              g_imp[BB * LL];
__device__ float              g_invn[BB * LL];
__device__ int                g_unp[BB * RR];
__device__ unsigned long long g_nodekey[BB * LH];
__device__ int                g_srctok[BB * RR];
__device__ int                g_dstj[BB * RR];
__device__ int                g_unm[BB * RR];
__device__ float              g_counts[BB * LH];
__device__ float              g_q[BB * UU];
__device__ float              g_m[BB * NH * DD];
__device__ float              g_cb[BB * NH];
__device__ float              g_logits[BB * NH * RR];
__device__ float              g_y[BB * NH * DD];
__device__ float              g_ctx[BB * UU];

__device__ __forceinline__ unsigned ford(float f) {
    unsigned u = __float_as_uint(f);
    return (u & 0x80000000u) ? ~u : (u | 0x80000000u);
}

// ---------------- K0: init accumulators (must run every replay) -----------
__global__ void k_init() {
    int i = blockIdx.x * blockDim.x + threadIdx.x;
    if (i < BB * LL) g_imp[i] = 0.f;
    if (i < BB * LH) { g_nodekey[i] = 0ull; g_counts[i] = 1.0f; }
}

// ---------------- K2: importance = column sums, diag removed --------------
// grid (8 row-chunks, 12 heads, 16 batch), 128 threads (4 cols each, float4)
__global__ void k_importance(const float* __restrict__ sc) {
    int b = blockIdx.z, h = blockIdx.y, chunk = blockIdx.x;
    int j0 = threadIdx.x * 4;
    const float* base = sc + (((size_t)b * HH + h) * LL + (size_t)chunk * 64) * LL;
    int i0 = chunk * 64;
    float a0 = 0.f, a1 = 0.f, a2 = 0.f, a3 = 0.f;
#pragma unroll 4
    for (int i = 0; i < 64; i++) {
        float4 v = *(const float4*)(base + (size_t)i * LL + j0);
        int gi = i0 + i;
        if (gi == j0)     v.x = 0.f;
        if (gi == j0 + 1) v.y = 0.f;
        if (gi == j0 + 2) v.z = 0.f;
        if (gi == j0 + 3) v.w = 0.f;
        a0 += v.x; a1 += v.y; a2 += v.z; a3 += v.w;
    }
    float* ip = g_imp + b * LL + j0;
    atomicAdd(ip + 0, a0); atomicAdd(ip + 1, a1);
    atomicAdd(ip + 2, a2); atomicAdd(ip + 3, a3);
}

// ---------------- K1: per-token inverse L2 norms ---------------------------
// grid (64, 16), 256 threads: one warp per row
__global__ void k_invnorm(const float* __restrict__ hid) {
    int warp = threadIdx.x >> 5, lane = threadIdx.x & 31;
    int row = blockIdx.x * 8 + warp;
    int b = blockIdx.y;
    const float4* p = (const float4*)(hid + ((size_t)b * LL + row) * DD);
    float s = 0.f;
#pragma unroll
    for (int it = 0; it < 6; it++) {
        float4 v = p[lane + it * 32];
        s += v.x * v.x + v.y * v.y + v.z * v.z + v.w * v.w;
    }
    for (int off = 16; off; off >>= 1) s += __shfl_xor_sync(0xffffffffu, s, off);
    if (lane == 0) g_invn[b * LL + row] = rsqrtf(s);
}

// ---------------- K3: top-K mask -> unpreserved idx (ascending) ------------
// grid 16, 512 threads. Rank-by-count with index tiebreak == lax.top_k.
__global__ void k_topk() {
    int b = blockIdx.x, t = threadIdx.x;
    __shared__ unsigned long long keys[LL];
    __shared__ int flags[LL];
    float v = g_imp[b * LL + t];
    unsigned long long key = ((unsigned long long)ford(v) << 32) | (unsigned)(0xFFFFFFFFu - t);
    keys[t] = key;
    __syncthreads();
    int rank = 0;
    for (int x = 0; x < LL; x++) rank += (keys[x] > key);
    int unp = (rank >= KP) ? 1 : 0;
    flags[t] = unp;
    __syncthreads();
    if (unp) {
        int pos = 0;
        for (int x = 0; x < t; x++) pos += flags[x];
        g_unp[b * RR + pos] = t;
    }
}

// ---------------- K4: cosine-sim GEMM + row max/argmax ---------------------
// C[i][j] = <na_i, nb_j>, a = even tokens, b = odd tokens, pre-normalized at
// smem-store time. 64x64 tile, 256 threads, 4x4 micro-tile (FP32 for exact
// rank preservation). Row argmax folded via packed atomicMax.
__global__ void k_sim(const float* __restrict__ hid) {
    int b = blockIdx.z, i0 = blockIdx.y * 64, j0 = blockIdx.x * 64;
    __shared__ float As[16][68];
    __shared__ float Bs[16][68];
    int tid = threadIdx.x;
    int tx = tid & 15, ty = tid >> 4;
    int lrow = tid >> 2, lseg = tid & 3;
    const float* base = hid + (size_t)b * LL * DD;
    float ia = g_invn[b * LL + 2 * (i0 + lrow)];
    float ib = g_invn[b * LL + 2 * (j0 + lrow) + 1];
    const float* arow = base + (size_t)(2 * (i0 + lrow)) * DD + lseg * 4;
    const float* brow = base + (size_t)(2 * (j0 + lrow) + 1) * DD + lseg * 4;

    float acc[4][4] = {};
    for (int k0 = 0; k0 < DD; k0 += 16) {
        float4 av = *(const float4*)(arow + k0);
        float4 bv = *(const float4*)(brow + k0);
        __syncthreads();
        As[lseg * 4 + 0][lrow] = av.x * ia;
        As[lseg * 4 + 1][lrow] = av.y * ia;
        As[lseg * 4 + 2][lrow] = av.z * ia;
        As[lseg * 4 + 3][lrow] = av.w * ia;
        Bs[lseg * 4 + 0][lrow] = bv.x * ib;
        Bs[lseg * 4 + 1][lrow] = bv.y * ib;
        Bs[lseg * 4 + 2][lrow] = bv.z * ib;
        Bs[lseg * 4 + 3][lrow] = bv.w * ib;
        __syncthreads();
#pragma unroll
        for (int kk = 0; kk < 16; kk++) {
            float a[4], c[4];
            *(float4*)a = *(const float4*)&As[kk][ty * 4];
            *(float4*)c = *(const float4*)&Bs[kk][tx * 4];
#pragma unroll
            for (int r = 0; r < 4; r++)
#pragma unroll
                for (int q = 0; q < 4; q++) acc[r][q] += a[r] * c[q];
        }
    }
    // per-row max/argmax (tie -> smaller j, matching jnp.argmax)
#pragma unroll
    for (int r = 0; r < 4; r++) {
        float best = acc[r][0]; int bc = 0;
        if (acc[r][1] > best) { best = acc[r][1]; bc = 1; }
        if (acc[r][2] > best) { best = acc[r][2]; bc = 2; }
        if (acc[r][3] > best) { best = acc[r][3]; bc = 3; }
        int j = j0 + tx * 4 + bc;
        unsigned long long key = ((unsigned long long)ford(best) << 32) | (unsigned)(255 - j);
        for (int off = 8; off; off >>= 1) {
            unsigned long long o = __shfl_xor_sync(0xffffffffu, key, off);
            if (o > key) key = o;
        }
        if (tx == 0) atomicMax(&g_nodekey[b * LH + i0 + ty * 4 + r], key);
    }
}

// ---------------- K5: stable descending edge argsort via rank counting -----
// grid 16, 256 threads. rank<128 -> src (position = rank), else unm.
__global__ void k_edges() {
    int b = blockIdx.x, i = threadIdx.x;
    __shared__ unsigned long long ek[LH];
    unsigned long long nk = g_nodekey[b * LH + i];
    int nidx = 255 - (int)(unsigned)(nk & 0xFFFFFFFFull);
    unsigned long long key = (nk & 0xFFFFFFFF00000000ull) | (unsigned)(255 - i);
    ek[i] = key;
    __syncthreads();
    int rank = 0;
    for (int x = 0; x < LH; x++) rank += (ek[x] > key);
    if (rank < RR) {
        g_srctok[b * RR + rank] = i;
        g_dstj[b * RR + rank] = nidx;
        atomicAdd(&g_counts[b * LH + nidx], 1.0f);
    } else {
        g_unm[b * RR + (rank - RR)] = i;
    }
}

// ---------------- K6: assemble output ---------------------------------------
__global__ void k_zero_dst(float* __restrict__ out) {
    int b = blockIdx.y, j = blockIdx.x;
    ((float4*)(out + ((size_t)b * OT + 129 + j) * DD))[threadIdx.x] = make_float4(0.f, 0.f, 0.f, 0.f);
}

__global__ void k_copy(const float* __restrict__ hid, float* __restrict__ out) {
    int b = blockIdx.y, v = blockIdx.x;                  // 0..128
    int srow = (v == 0) ? 0 : 2 * g_unm[b * RR + (v - 1)];
    const float4* s = (const float4*)(hid + ((size_t)b * LL + srow) * DD);
    float4* d = (float4*)(out + ((size_t)b * OT + v) * DD);
    d[threadIdx.x] = s[threadIdx.x];
}

__global__ void k_scatter(const float* __restrict__ hid, float* __restrict__ out) {
    int b = blockIdx.y, p = blockIdx.x;                  // 0..127
    int s = g_srctok[b * RR + p], dj = g_dstj[b * RR + p];
    const float* src = hid + ((size_t)b * LL + 2 * s) * DD;
    float* dst = out + ((size_t)b * OT + 129 + dj) * DD;
    int d0 = threadIdx.x * 4;
    float4 v = *(const float4*)(src + d0);
    atomicAdd(dst + d0 + 0, v.x);
    atomicAdd(dst + d0 + 1, v.y);
    atomicAdd(dst + d0 + 2, v.z);
    atomicAdd(dst + d0 + 3, v.w);
}

__global__ void k_merge(const float* __restrict__ hid, float* __restrict__ out) {
    int b = blockIdx.y, j = blockIdx.x;                  // 0..255
    float c = g_counts[b * LH + j];
    int d0 = threadIdx.x * 4;
    float* o = out + ((size_t)b * OT + 129 + j) * DD + d0;
    float4 a = *(float4*)o;
    float4 x = *(const float4*)(hid + ((size_t)b * LL + 2 * j + 1) * DD + d0);
    a.x = (a.x + x.x) / c; a.y = (a.y + x.y) / c;
    a.z = (a.z + x.z) / c; a.w = (a.w + x.w) / c;
    *(float4*)o = a;
}

// ---------------- attention (refactored) ------------------------------------
// q = cls @ Wq + bq        grid 16, 384 threads
__global__ void k_q(const float* __restrict__ hid, const float* __restrict__ Wq,
                    const float* __restrict__ bq) {
    int b = blockIdx.x, u = threadIdx.x;
    __shared__ float cls[DD];
    cls[u] = hid[(size_t)b * LL * DD + u];
    cls[u + UU] = hid[(size_t)b * LL * DD + UU + u];
    __syncthreads();
    float a0 = bq[u], a1 = 0.f;
#pragma unroll 4
    for (int k = 0; k < DD; k += 2) {
        a0 += cls[k] * Wq[(size_t)k * UU + u];
        a1 += cls[k + 1] * Wq[(size_t)(k + 1) * UU + u];
    }
    g_q[b * UU + u] = a0 + a1;
}

// m[b,h,:] = Wk_h @ q_h ; cbias = q_h . bk_h     grid (6,16), 768 threads
__global__ void k_m(const float* __restrict__ Wk, const float* __restrict__ bk) {
    int h = blockIdx.x, b = blockIdx.y, t = threadIdx.x;
    __shared__ float sq[HD];
    __shared__ float sp[HD];
    if (t < HD) sq[t] = g_q[b * UU + h * HD + t];
    __syncthreads();
    float acc = 0.f;
    const float* wrow = Wk + (size_t)t * UU + h * HD;
#pragma unroll
    for (int u = 0; u < HD; u += 4) {
        float4 wv = *(const float4*)(wrow + u);
        acc += wv.x * sq[u] + wv.y * sq[u + 1] + wv.z * sq[u + 2] + wv.w * sq[u + 3];
    }
    g_m[((size_t)b * NH + h) * DD + t] = acc;
    if (t < HD) sp[t] = sq[t] * bk[h * HD + t];
    __syncthreads();
    if (t == 0) {
        float c = 0.f;
        for (int u = 0; u < HD; u++) c += sp[u];
        g_cb[b * NH + h] = c;
    }
}

// logits[b,h,t] = (x_t . m_bh + cbias) / 8      one warp per (b,t)
__global__ void k_logits(const float* __restrict__ hid) {
    int w = (blockIdx.x * blockDim.x + threadIdx.x) >> 5;
    int lane = threadIdx.x & 31;
    if (w >= BB * RR) return;
    int b = w >> 7, t = w & 127;
    int row = g_unp[b * RR + t];
    const float* x = hid + ((size_t)b * LL + row) * DD;
    const float* m = g_m + (size_t)b * NH * DD;
    float acc[NH] = {};
    for (int k = lane; k < DD; k += 32) {
        float xv = x[k];
#pragma unroll
        for (int h = 0; h < NH; h++) acc[h] += xv * m[h * DD + k];
    }
#pragma unroll
    for (int h = 0; h < NH; h++)
        for (int off = 16; off; off >>= 1) acc[h] += __shfl_xor_sync(0xffffffffu, acc[h], off);
    if (lane == 0) {
#pragma unroll
        for (int h = 0; h < NH; h++)
            g_logits[((size_t)b * NH + h) * RR + t] = (acc[h] + g_cb[b * NH + h]) * 0.125f;
    }
}

// softmax over 128 keys, then y[b,h,:] = sum_t w_t * x_t   grid (6,16), 256 thr
__global__ void k_smax_y(const float* __restrict__ hid) {
    int h = blockIdx.x, b = blockIdx.y, t = threadIdx.x;
    __shared__ float w[RR];
    __shared__ int su[RR];
    __shared__ float red[8];
    if (t < RR) {
        w[t] = g_logits[((size_t)b * NH + h) * RR + t];
        su[t] = g_unp[b * RR + t];
    }
    __syncthreads();
    if (t < RR) {
        float m = w[t];
        for (int off = 16; off; off >>= 1) m = fmaxf(m, __shfl_xor_sync(0xffffffffu, m, off));
        if ((t & 31) == 0) red[t >> 5] = m;
    }
    __syncthreads();
    float mx = fmaxf(fmaxf(red[0], red[1]), fmaxf(red[2], red[3]));
    float e = 0.f;
    if (t < RR) e = expf(w[t] - mx);
    float s = e;
    for (int off = 16; off; off >>= 1) s += __shfl_xor_sync(0xffffffffu, s, off);
    if (t < RR && (t & 31) == 0) red[4 + (t >> 5)] = s;
    __syncthreads();
    float tot = red[4] + red[5] + red[6] + red[7];
    if (t < RR) w[t] = e / tot;
    __syncthreads();
    for (int d = t; d < DD; d += 256) {
        float acc = 0.f;
#pragma unroll 4
        for (int tt = 0; tt < RR; tt++)
            acc += w[tt] * hid[((size_t)b * LL + su[tt]) * DD + d];
        g_y[((size_t)b * NH + h) * DD + d] = acc;
    }
}

// ctx[b,u] = y[b,h(u),:] . Wv[:,u] + bv[u]    grid 16, 384 threads
__global__ void k_ctx(const float* __restrict__ Wv, const float* __restrict__ bv) {
    int b = blockIdx.x, u = threadIdx.x;
    __shared__ float sy[NH * DD];
    for (int i = u; i < NH * DD; i += UU) sy[i] = g_y[(size_t)b * NH * DD + i];
    __syncthreads();
    int h = u >> 6;
    float acc = bv[u];
#pragma unroll 4
    for (int d = 0; d < DD; d++) acc += sy[h * DD + d] * Wv[(size_t)d * UU + u];
    g_ctx[b * UU + u] = acc;
}

// new_token = ctx @ Wo + bo -> out row 385    grid 16, 768 threads
__global__ void k_newtok(const float* __restrict__ Wo, const float* __restrict__ bo,
                         float* __restrict__ out) {
    int b = blockIdx.x, d = threadIdx.x;
    __shared__ float sc[UU];
    if (d < UU) sc[d] = g_ctx[b * UU + d];
    __syncthreads();
    float acc = bo[d];
#pragma unroll 4
    for (int u = 0; u < UU; u++) acc += sc[u] * Wo[(size_t)u * DD + d];
    out[((size_t)b * OT + 385) * DD + d] = acc;
}

// ---------------- launch ----------------------------------------------------
extern "C" void kernel_launch(void* const* d_in, const int* in_sizes, int n_in,
                              void* d_out, int out_size) {
    (void)in_sizes; (void)n_in; (void)out_size;
    const float* hid = (const float*)d_in[0];
    const float* sc  = (const float*)d_in[1];
    const float* Wq  = (const float*)d_in[2];
    const float* bq  = (const float*)d_in[3];
    const float* Wk  = (const float*)d_in[4];
    const float* bk  = (const float*)d_in[5];
    const float* Wv  = (const float*)d_in[6];
    const float* bv  = (const float*)d_in[7];
    const float* Wo  = (const float*)d_in[8];
    const float* bo  = (const float*)d_in[9];
    float* out = (float*)d_out;

    k_init<<<32, 256>>>();
    k_importance<<<dim3(8, HH, BB), 128>>>(sc);
    k_invnorm<<<dim3(64, BB), 256>>>(hid);
    k_topk<<<BB, 512>>>();
    k_sim<<<dim3(4, 4, BB), 256>>>(hid);
    k_edges<<<BB, 256>>>();
    k_zero_dst<<<dim3(LH, BB), 192>>>(out);
    k_copy<<<dim3(129, BB), 192>>>(hid, out);
    k_scatter<<<dim3(RR, BB), 192>>>(hid, out);
    k_merge<<<dim3(LH, BB), 192>>>(hid, out);
    k_q<<<BB, UU>>>(hid, Wq, bq);
    k_m<<<dim3(NH, BB), DD>>>(Wk, bk);
    k_logits<<<256, 256>>>(hid);
    k_smax_y<<<dim3(NH, BB), 256>>>(hid);
    k_ctx<<<BB, UU>>>(Wv, bv);
    k_newtok<<<BB, DD>>>(Wo, bo, out);
}

// round 7
// speedup vs baseline: 1.0164x; 1.0137x over previous
#include <cuda_runtime.h>
#include <cstdint>

// Problem constants
#define BB 16
#define LL 512
#define DD 768
#define HH 12
#define UU 384
#define NH 6
#define HD 64
#define KP 384
#define RR 128        // L - K  (merged count == unpreserved count)
#define LH 256        // L/2
#define OT 386        // output tokens per batch

// ---------------- device scratch (static, allocation-free) ----------------
__device__ float              g_imp[BB * LL];
__device__ float              g_invn[BB * LL];
__device__ int                g_unp[BB * RR];
__device__ unsigned long long g_nodekey[BB * LH];
__device__ int                g_srctok[BB * RR];
__device__ int                g_dstj[BB * RR];
__device__ int                g_unm[BB * RR];
__device__ float              g_counts[BB * LH];
__device__ float              g_q[BB * UU];
__device__ float              g_m[BB * NH * DD];
__device__ float              g_cb[BB * NH];
__device__ float              g_logits[BB * NH * RR];
__device__ float              g_y[BB * NH * DD];
__device__ float              g_ctx[BB * UU];

__device__ __forceinline__ unsigned ford(float f) {
    unsigned u = __float_as_uint(f);
    return (u & 0x80000000u) ? ~u : (u | 0x80000000u);
}

// ---------------- K0: init accumulators (must run every replay) -----------
__global__ void k_init() {
    int i = blockIdx.x * blockDim.x + threadIdx.x;
    if (i < BB * LL) g_imp[i] = 0.f;
    if (i < BB * LH) { g_nodekey[i] = 0ull; g_counts[i] = 1.0f; }
}

// ---------------- K2: importance = column sums, diag removed --------------
// grid (8 row-chunks, 12 heads, 16 batch), 128 threads (4 cols each, float4)
__global__ void k_importance(const float* __restrict__ sc) {
    int b = blockIdx.z, h = blockIdx.y, chunk = blockIdx.x;
    int j0 = threadIdx.x * 4;
    const float* base = sc + (((size_t)b * HH + h) * LL + (size_t)chunk * 64) * LL;
    int i0 = chunk * 64;
    float a0 = 0.f, a1 = 0.f, a2 = 0.f, a3 = 0.f;
#pragma unroll 4
    for (int i = 0; i < 64; i++) {
        float4 v = *(const float4*)(base + (size_t)i * LL + j0);
        int gi = i0 + i;
        if (gi == j0)     v.x = 0.f;
        if (gi == j0 + 1) v.y = 0.f;
        if (gi == j0 + 2) v.z = 0.f;
        if (gi == j0 + 3) v.w = 0.f;
        a0 += v.x; a1 += v.y; a2 += v.z; a3 += v.w;
    }
    float* ip = g_imp + b * LL + j0;
    atomicAdd(ip + 0, a0); atomicAdd(ip + 1, a1);
    atomicAdd(ip + 2, a2); atomicAdd(ip + 3, a3);
}

// ---------------- K1: per-token inverse L2 norms ---------------------------
// grid (64, 16), 256 threads: one warp per row
__global__ void k_invnorm(const float* __restrict__ hid) {
    int warp = threadIdx.x >> 5, lane = threadIdx.x & 31;
    int row = blockIdx.x * 8 + warp;
    int b = blockIdx.y;
    const float4* p = (const float4*)(hid + ((size_t)b * LL + row) * DD);
    float s = 0.f;
#pragma unroll
    for (int it = 0; it < 6; it++) {
        float4 v = p[lane + it * 32];
        s += v.x * v.x + v.y * v.y + v.z * v.z + v.w * v.w;
    }
    for (int off = 16; off; off >>= 1) s += __shfl_xor_sync(0xffffffffu, s, off);
    if (lane == 0) g_invn[b * LL + row] = rsqrtf(s);
}

// ---------------- K3: top-K mask -> unpreserved idx (ascending) ------------
// grid 16, 512 threads. Rank-by-count with index tiebreak == lax.top_k.
__global__ void k_topk() {
    int b = blockIdx.x, t = threadIdx.x;
    __shared__ unsigned long long keys[LL];
    __shared__ int flags[LL];
    float v = g_imp[b * LL + t];
    unsigned long long key = ((unsigned long long)ford(v) << 32) | (unsigned)(0xFFFFFFFFu - t);
    keys[t] = key;
    __syncthreads();
    int rank = 0;
    for (int x = 0; x < LL; x++) rank += (keys[x] > key);
    int unp = (rank >= KP) ? 1 : 0;
    flags[t] = unp;
    __syncthreads();
    if (unp) {
        int pos = 0;
        for (int x = 0; x < t; x++) pos += flags[x];
        g_unp[b * RR + pos] = t;
    }
}

// ---------------- K4: cosine-sim GEMM + row max/argmax ---------------------
// C[i][j] = <na_i, nb_j>, a = even tokens, b = odd tokens, pre-normalized at
// smem-store time. 64x64 tile, 256 threads, 4x4 micro-tile (FP32 for exact
// rank preservation). Row argmax folded via packed atomicMax.
__global__ void k_sim(const float* __restrict__ hid) {
    int b = blockIdx.z, i0 = blockIdx.y * 64, j0 = blockIdx.x * 64;
    __shared__ float As[16][68];
    __shared__ float Bs[16][68];
    int tid = threadIdx.x;
    int tx = tid & 15, ty = tid >> 4;
    int lrow = tid >> 2, lseg = tid & 3;
    const float* base = hid + (size_t)b * LL * DD;
    float ia = g_invn[b * LL + 2 * (i0 + lrow)];
    float ib = g_invn[b * LL + 2 * (j0 + lrow) + 1];
    const float* arow = base + (size_t)(2 * (i0 + lrow)) * DD + lseg * 4;
    const float* brow = base + (size_t)(2 * (j0 + lrow) + 1) * DD + lseg * 4;

    float acc[4][4] = {};
    for (int k0 = 0; k0 < DD; k0 += 16) {
        float4 av = *(const float4*)(arow + k0);
        float4 bv = *(const float4*)(brow + k0);
        __syncthreads();
        As[lseg * 4 + 0][lrow] = av.x * ia;
        As[lseg * 4 + 1][lrow] = av.y * ia;
        As[lseg * 4 + 2][lrow] = av.z * ia;
        As[lseg * 4 + 3][lrow] = av.w * ia;
        Bs[lseg * 4 + 0][lrow] = bv.x * ib;
        Bs[lseg * 4 + 1][lrow] = bv.y * ib;
        Bs[lseg * 4 + 2][lrow] = bv.z * ib;
        Bs[lseg * 4 + 3][lrow] = bv.w * ib;
        __syncthreads();
#pragma unroll
        for (int kk = 0; kk < 16; kk++) {
            float a[4], c[4];
            *(float4*)a = *(const float4*)&As[kk][ty * 4];
            *(float4*)c = *(const float4*)&Bs[kk][tx * 4];
#pragma unroll
            for (int r = 0; r < 4; r++)
#pragma unroll
                for (int q = 0; q < 4; q++) acc[r][q] += a[r] * c[q];
        }
    }
    // per-row max/argmax (tie -> smaller j, matching jnp.argmax)
#pragma unroll
    for (int r = 0; r < 4; r++) {
        float best = acc[r][0]; int bc = 0;
        if (acc[r][1] > best) { best = acc[r][1]; bc = 1; }
        if (acc[r][2] > best) { best = acc[r][2]; bc = 2; }
        if (acc[r][3] > best) { best = acc[r][3]; bc = 3; }
        int j = j0 + tx * 4 + bc;
        unsigned long long key = ((unsigned long long)ford(best) << 32) | (unsigned)(255 - j);
        for (int off = 8; off; off >>= 1) {
            unsigned long long o = __shfl_xor_sync(0xffffffffu, key, off);
            if (o > key) key = o;
        }
        if (tx == 0) atomicMax(&g_nodekey[b * LH + i0 + ty * 4 + r], key);
    }
}

// ---------------- K5: stable descending edge argsort via rank counting -----
// grid 16, 256 threads. rank<128 -> src (position = rank), else unm.
__global__ void k_edges() {
    int b = blockIdx.x, i = threadIdx.x;
    __shared__ unsigned long long ek[LH];
    unsigned long long nk = g_nodekey[b * LH + i];
    int nidx = 255 - (int)(unsigned)(nk & 0xFFFFFFFFull);
    unsigned long long key = (nk & 0xFFFFFFFF00000000ull) | (unsigned)(255 - i);
    ek[i] = key;
    __syncthreads();
    int rank = 0;
    for (int x = 0; x < LH; x++) rank += (ek[x] > key);
    if (rank < RR) {
        g_srctok[b * RR + rank] = i;
        g_dstj[b * RR + rank] = nidx;
        atomicAdd(&g_counts[b * LH + nidx], 1.0f);
    } else {
        g_unm[b * RR + (rank - RR)] = i;
    }
}

// ---------------- K6: assemble output ---------------------------------------
__global__ void k_zero_dst(float* __restrict__ out) {
    int b = blockIdx.y, j = blockIdx.x;
    ((float4*)(out + ((size_t)b * OT + 129 + j) * DD))[threadIdx.x] = make_float4(0.f, 0.f, 0.f, 0.f);
}

__global__ void k_copy(const float* __restrict__ hid, float* __restrict__ out) {
    int b = blockIdx.y, v = blockIdx.x;                  // 0..128
    int srow = (v == 0) ? 0 : 2 * g_unm[b * RR + (v - 1)];
    const float4* s = (const float4*)(hid + ((size_t)b * LL + srow) * DD);
    float4* d = (float4*)(out + ((size_t)b * OT + v) * DD);
    d[threadIdx.x] = s[threadIdx.x];
}

__global__ void k_scatter(const float* __restrict__ hid, float* __restrict__ out) {
    int b = blockIdx.y, p = blockIdx.x;                  // 0..127
    int s = g_srctok[b * RR + p], dj = g_dstj[b * RR + p];
    const float* src = hid + ((size_t)b * LL + 2 * s) * DD;
    float* dst = out + ((size_t)b * OT + 129 + dj) * DD;
    int d0 = threadIdx.x * 4;
    float4 v = *(const float4*)(src + d0);
    atomicAdd(dst + d0 + 0, v.x);
    atomicAdd(dst + d0 + 1, v.y);
    atomicAdd(dst + d0 + 2, v.z);
    atomicAdd(dst + d0 + 3, v.w);
}

__global__ void k_merge(const float* __restrict__ hid, float* __restrict__ out) {
    int b = blockIdx.y, j = blockIdx.x;                  // 0..255
    float c = g_counts[b * LH + j];
    int d0 = threadIdx.x * 4;
    float* o = out + ((size_t)b * OT + 129 + j) * DD + d0;
    float4 a = *(float4*)o;
    float4 x = *(const float4*)(hid + ((size_t)b * LL + 2 * j + 1) * DD + d0);
    a.x = (a.x + x.x) / c; a.y = (a.y + x.y) / c;
    a.z = (a.z + x.z) / c; a.w = (a.w + x.w) / c;
    *(float4*)o = a;
}

// ---------------- attention (refactored) ------------------------------------
// q = cls @ Wq + bq        grid 16, 384 threads
__global__ void k_q(const float* __restrict__ hid, const float* __restrict__ Wq,
                    const float* __restrict__ bq) {
    int b = blockIdx.x, u = threadIdx.x;
    __shared__ float cls[DD];
    cls[u] = hid[(size_t)b * LL * DD + u];
    cls[u + UU] = hid[(size_t)b * LL * DD + UU + u];
    __syncthreads();
    float a0 = bq[u], a1 = 0.f;
#pragma unroll 4
    for (int k = 0; k < DD; k += 2) {
        a0 += cls[k] * Wq[(size_t)k * UU + u];
        a1 += cls[k + 1] * Wq[(size_t)(k + 1) * UU + u];
    }
    g_q[b * UU + u] = a0 + a1;
}

// m[b,h,:] = Wk_h @ q_h ; cbias = q_h . bk_h     grid (6,16), 768 threads
__global__ void k_m(const float* __restrict__ Wk, const float* __restrict__ bk) {
    int h = blockIdx.x, b = blockIdx.y, t = threadIdx.x;
    __shared__ float sq[HD];
    __shared__ float sp[HD];
    if (t < HD) sq[t] = g_q[b * UU + h * HD + t];
    __syncthreads();
    float acc = 0.f;
    const float* wrow = Wk + (size_t)t * UU + h * HD;
#pragma unroll
    for (int u = 0; u < HD; u += 4) {
        float4 wv = *(const float4*)(wrow + u);
        acc += wv.x * sq[u] + wv.y * sq[u + 1] + wv.z * sq[u + 2] + wv.w * sq[u + 3];
    }
    g_m[((size_t)b * NH + h) * DD + t] = acc;
    if (t < HD) sp[t] = sq[t] * bk[h * HD + t];
    __syncthreads();
    if (t == 0) {
        float c = 0.f;
        for (int u = 0; u < HD; u++) c += sp[u];
        g_cb[b * NH + h] = c;
    }
}

// logits[b,h,t] = (x_t . m_bh + cbias) / 8      one warp per (b,t)
__global__ void k_logits(const float* __restrict__ hid) {
    int w = (blockIdx.x * blockDim.x + threadIdx.x) >> 5;
    int lane = threadIdx.x & 31;
    if (w >= BB * RR) return;
    int b = w >> 7, t = w & 127;
    int row = g_unp[b * RR + t];
    const float* x = hid + ((size_t)b * LL + row) * DD;
    const float* m = g_m + (size_t)b * NH * DD;
    float acc[NH] = {};
    for (int k = lane; k < DD; k += 32) {
        float xv = x[k];
#pragma unroll
        for (int h = 0; h < NH; h++) acc[h] += xv * m[h * DD + k];
    }
#pragma unroll
    for (int h = 0; h < NH; h++)
        for (int off = 16; off; off >>= 1) acc[h] += __shfl_xor_sync(0xffffffffu, acc[h], off);
    if (lane == 0) {
#pragma unroll
        for (int h = 0; h < NH; h++)
            g_logits[((size_t)b * NH + h) * RR + t] = (acc[h] + g_cb[b * NH + h]) * 0.125f;
    }
}

// softmax over 128 keys, then y[b,h,:] = sum_t w_t * x_t   grid (6,16), 256 thr
__global__ void k_smax_y(const float* __restrict__ hid) {
    int h = blockIdx.x, b = blockIdx.y, t = threadIdx.x;
    __shared__ float w[RR];
    __shared__ int su[RR];
    __shared__ float red[8];
    if (t < RR) {
        w[t] = g_logits[((size_t)b * NH + h) * RR + t];
        su[t] = g_unp[b * RR + t];
    }
    __syncthreads();
    if (t < RR) {
        float m = w[t];
        for (int off = 16; off; off >>= 1) m = fmaxf(m, __shfl_xor_sync(0xffffffffu, m, off));
        if ((t & 31) == 0) red[t >> 5] = m;
    }
    __syncthreads();
    float mx = fmaxf(fmaxf(red[0], red[1]), fmaxf(red[2], red[3]));
    float e = 0.f;
    if (t < RR) e = expf(w[t] - mx);
    float s = e;
    for (int off = 16; off; off >>= 1) s += __shfl_xor_sync(0xffffffffu, s, off);
    if (t < RR && (t & 31) == 0) red[4 + (t >> 5)] = s;
    __syncthreads();
    float tot = red[4] + red[5] + red[6] + red[7];
    if (t < RR) w[t] = e / tot;
    __syncthreads();
    for (int d = t; d < DD; d += 256) {
        float acc = 0.f;
#pragma unroll 4
        for (int tt = 0; tt < RR; tt++)
            acc += w[tt] * hid[((size_t)b * LL + su[tt]) * DD + d];
        g_y[((size_t)b * NH + h) * DD + d] = acc;
    }
}

// ctx[b,u] = y[b,h(u),:] . Wv[:,u] + bv[u]    grid 16, 384 threads
__global__ void k_ctx(const float* __restrict__ Wv, const float* __restrict__ bv) {
    int b = blockIdx.x, u = threadIdx.x;
    __shared__ float sy[NH * DD];
    for (int i = u; i < NH * DD; i += UU) sy[i] = g_y[(size_t)b * NH * DD + i];
    __syncthreads();
    int h = u >> 6;
    float acc = bv[u];
#pragma unroll 4
    for (int d = 0; d < DD; d++) acc += sy[h * DD + d] * Wv[(size_t)d * UU + u];
    g_ctx[b * UU + u] = acc;
}

// new_token = ctx @ Wo + bo -> out row 385    grid 16, 768 threads
__global__ void k_newtok(const float* __restrict__ Wo, const float* __restrict__ bo,
                         float* __restrict__ out) {
    int b = blockIdx.x, d = threadIdx.x;
    __shared__ float sc[UU];
    if (d < UU) sc[d] = g_ctx[b * UU + d];
    __syncthreads();
    float acc = bo[d];
#pragma unroll 4
    for (int u = 0; u < UU; u++) acc += sc[u] * Wo[(size_t)u * DD + d];
    out[((size_t)b * OT + 385) * DD + d] = acc;
}

// ---------------- launch ----------------------------------------------------
extern "C" void kernel_launch(void* const* d_in, const int* in_sizes, int n_in,
                              void* d_out, int out_size) {
    (void)in_sizes; (void)n_in; (void)out_size;
    const float* hid = (const float*)d_in[0];
    const float* sc  = (const float*)d_in[1];
    const float* Wq  = (const float*)d_in[2];
    const float* bq  = (const float*)d_in[3];
    const float* Wk  = (const float*)d_in[4];
    const float* bk  = (const float*)d_in[5];
    const float* Wv  = (const float*)d_in[6];
    const float* bv  = (const float*)d_in[7];
    const float* Wo  = (const float*)d_in[8];
    const float* bo  = (const float*)d_in[9];
    float* out = (float*)d_out;

    k_init<<<32, 256>>>();
    k_importance<<<dim3(8, HH, BB), 128>>>(sc);
    k_invnorm<<<dim3(64, BB), 256>>>(hid);
    k_topk<<<BB, 512>>>();
    k_sim<<<dim3(4, 4, BB), 256>>>(hid);
    k_edges<<<BB, 256>>>();
    k_zero_dst<<<dim3(LH, BB), 192>>>(out);
    k_copy<<<dim3(129, BB), 192>>>(hid, out);
    k_scatter<<<dim3(RR, BB), 192>>>(hid, out);
    k_merge<<<dim3(LH, BB), 192>>>(hid, out);
    k_q<<<BB, UU>>>(hid, Wq, bq);
    k_m<<<dim3(NH, BB), DD>>>(Wk, bk);
    k_logits<<<256, 256>>>(hid);
    k_smax_y<<<dim3(NH, BB), 256>>>(hid);
    k_ctx<<<BB, UU>>>(Wv, bv);
    k_newtok<<<BB, DD>>>(Wo, bo, out);
}